// round 4
// baseline (speedup 1.0000x reference)
#include <cuda_runtime.h>

#define Bv 64
#define Tv 2048
#define Cv 1
#define Nv 128

__device__ __forceinline__ void ffma2(unsigned long long& d,
                                      unsigned long long a,
                                      unsigned long long b) {
    asm("fma.rn.f32x2 %0, %1, %2, %0;" : "+l"(d) : "l"(a), "l"(b));
}
__device__ __forceinline__ void fadd2(unsigned long long& d, unsigned long long a) {
    asm("add.rn.f32x2 %0, %0, %1;" : "+l"(d) : "l"(a));
}
__device__ __forceinline__ unsigned long long pack2(float a, float b) {
    unsigned long long r;
    asm("mov.b64 %0, {%1, %2};" : "=l"(r) : "f"(a), "f"(b));
    return r;
}
__device__ __forceinline__ float2 unpack2(unsigned long long v) {
    float2 r;
    asm("mov.b64 {%0, %1}, %2;" : "=f"(r.x), "=f"(r.y) : "l"(v));
    return r;
}
__device__ __forceinline__ float lo32(unsigned long long v) {
    float r;
    asm("{ .reg .f32 hi; mov.b64 {%0, hi}, %1; }" : "=f"(r) : "l"(v));
    return r;
}

// Epilogue: exact power-of-2 rescale from previous W[0]'s exponent.
__device__ __forceinline__ float finish_step(unsigned long long s0, unsigned long long s1,
                                             unsigned long long s2, unsigned long long s3,
                                             float w0, float ex_cur, float& logM) {
    fadd2(s0, s1); fadd2(s2, s3); fadd2(s0, s2);
    float2 sp = unpack2(s0);
    float s = sp.x + sp.y;
    int ebits = __float_as_int(w0) & 0x7f800000;
    float inv_r = __int_as_float(0x7f000000 - ebits);   // 2^(127 - E)
    logM += (float)((ebits >> 23) - 127) * 0.693147180559945f;
    return s * (ex_cur * inv_r);
}

// Single-sequence matvec step (tail path when the partner sequence expired).
__device__ __forceinline__ float step_one(const float* Wp,
                                          const unsigned long long (&e2)[Nv / 2],
                                          float ex_cur, float& logM) {
    const ulonglong2* Wv = reinterpret_cast<const ulonglong2*>(Wp);
    ulonglong2 w = Wv[0];
    float w0 = lo32(w.x);
    unsigned long long s0 = 0ull, s1 = 0ull, s2 = 0ull, s3 = 0ull;
    ffma2(s0, w.x, e2[0]);
    ffma2(s1, w.y, e2[1]);
    #pragma unroll
    for (int k = 1; k < Nv / 4; ++k) {
        w = Wv[k];
        if ((k & 1) == 0) { ffma2(s0, w.x, e2[2 * k]); ffma2(s1, w.y, e2[2 * k + 1]); }
        else              { ffma2(s2, w.x, e2[2 * k]); ffma2(s3, w.y, e2[2 * k + 1]); }
    }
    return finish_step(s0, s1, s2, s3, w0, ex_cur, logM);
}

// Two CTAs' worth of sequences per CTA, interleaved so each recurrence's
// latency chain hides under the other's issue stream. E (exp of transitions)
// is shared between both sequences in registers.
__global__ __launch_bounds__(Nv, 1)
void crf_fwd(const float* __restrict__ emissions,
             const int* __restrict__ token_sizes,
             const float* __restrict__ transitions,
             const float* __restrict__ head,
             const float* __restrict__ last,
             float* __restrict__ out)
{
    const int bc = blockIdx.x;          // 0..31
    const int b0 = 2 * bc, b1 = 2 * bc + 1;
    const int n = threadIdx.x;

    __shared__ __align__(16) float W0[2][Nv];
    __shared__ __align__(16) float W1[2][Nv];
    __shared__ float red[8];

    // Pack column n of exp(transitions) as 64 f32x2 register pairs (shared by both seqs).
    unsigned long long e2[Nv / 2];
    #pragma unroll
    for (int k = 0; k < Nv / 2; ++k) {
        float lo = __expf(transitions[(2 * k + 0) * Nv + n]);
        float hi = __expf(transitions[(2 * k + 1) * Nv + n]);
        e2[k] = pack2(lo, hi);
    }

    const int len0 = token_sizes[b0];
    const int len1 = token_sizes[b1];
    const int lenmax = max(len0, len1);
    const int ts = Cv * Nv;
    const float* em0 = emissions + ((size_t)b0 * Tv) * ts + n;
    const float* em1 = emissions + ((size_t)b1 * Tv) * ts + n;

    // t = 0 init for both sequences.
    float h = head[n];
    float a00 = h + em0[0];
    float a10 = h + em1[0];
    W0[0][n] = a00;
    W1[0][n] = a10;
    __syncthreads();
    float K0 = W0[0][0], K1 = W1[0][0];
    float logM0 = K0, logM1 = K1;
    W0[1][n] = __expf(a00 - K0);
    W1[1][n] = __expf(a10 - K1);
    __syncthreads();
    int p = 1;

    // Distance-2 emission prefetch for both sequences.
    float ex0 = __expf(em0[ts]);
    float ex1 = __expf(em1[ts]);
    float nx0 = em0[min(2, Tv - 1) * ts];
    float nx1 = em1[min(2, Tv - 1) * ts];

    for (int t = 1; t < lenmax; ++t) {
        const bool act0 = t < len0, act1 = t < len1;   // uniform across CTA

        if (act0 & act1) {
            // Fused step: interleave the two dot products.
            const ulonglong2* Wa = reinterpret_cast<const ulonglong2*>(W0[p]);
            const ulonglong2* Wb = reinterpret_cast<const ulonglong2*>(W1[p]);
            ulonglong2 wa = Wa[0], wb = Wb[0];
            float w00 = lo32(wa.x), w10 = lo32(wb.x);
            unsigned long long a0 = 0ull, a1 = 0ull, a2 = 0ull, a3 = 0ull;
            unsigned long long c0 = 0ull, c1 = 0ull, c2 = 0ull, c3 = 0ull;
            ffma2(a0, wa.x, e2[0]); ffma2(c0, wb.x, e2[0]);
            ffma2(a1, wa.y, e2[1]); ffma2(c1, wb.y, e2[1]);
            #pragma unroll
            for (int k = 1; k < Nv / 4; ++k) {
                wa = Wa[k]; wb = Wb[k];
                if ((k & 1) == 0) {
                    ffma2(a0, wa.x, e2[2 * k]);     ffma2(c0, wb.x, e2[2 * k]);
                    ffma2(a1, wa.y, e2[2 * k + 1]); ffma2(c1, wb.y, e2[2 * k + 1]);
                } else {
                    ffma2(a2, wa.x, e2[2 * k]);     ffma2(c2, wb.x, e2[2 * k]);
                    ffma2(a3, wa.y, e2[2 * k + 1]); ffma2(c3, wb.y, e2[2 * k + 1]);
                }
            }
            W0[p ^ 1][n] = finish_step(a0, a1, a2, a3, w00, ex0, logM0);
            W1[p ^ 1][n] = finish_step(c0, c1, c2, c3, w10, ex1, logM1);
        } else if (act0) {
            W0[p ^ 1][n] = step_one(W0[p], e2, ex0, logM0);
            W1[p ^ 1][n] = W1[p][n];
        } else {
            W1[p ^ 1][n] = step_one(W1[p], e2, ex1, logM1);
            W0[p ^ 1][n] = W0[p][n];
        }

        // Advance emission prefetch pipelines (clamped; unused past len).
        ex0 = __expf(nx0);
        ex1 = __expf(nx1);
        int tn = min(t + 2, Tv - 1) * ts;
        nx0 = em0[tn];
        nx1 = em1[tn];

        __syncthreads();
        p ^= 1;
    }

    // Finalize both sequences: out = logM + log(sum_n W[n] * exp(last[n]))
    float el = __expf(last[n]);
    float t0 = W0[p][n] * el;
    float t1 = W1[p][n] * el;
    #pragma unroll
    for (int o = 16; o > 0; o >>= 1) {
        t0 += __shfl_down_sync(0xffffffffu, t0, o);
        t1 += __shfl_down_sync(0xffffffffu, t1, o);
    }
    if ((n & 31) == 0) { red[n >> 5] = t0; red[4 + (n >> 5)] = t1; }
    __syncthreads();
    if (n == 0) {
        float s0 = (red[0] + red[1]) + (red[2] + red[3]);
        float s1 = (red[4] + red[5]) + (red[6] + red[7]);
        out[b0] = logM0 + logf(s0);
        out[b1] = logM1 + logf(s1);
    }
}

extern "C" void kernel_launch(void* const* d_in, const int* in_sizes, int n_in,
                              void* d_out, int out_size) {
    const float* emissions   = (const float*)d_in[0];
    const int*   token_sizes = (const int*)d_in[1];
    const float* transitions = (const float*)d_in[2];
    const float* head        = (const float*)d_in[3];
    const float* last        = (const float*)d_in[4];
    crf_fwd<<<Bv / 2, Nv>>>(emissions, token_sizes, transitions, head, last,
                            (float*)d_out);
}

// round 5
// speedup vs baseline: 1.4028x; 1.4028x over previous
#include <cuda_runtime.h>

#define Bv 64
#define Tv 2048
#define Nv 128
#define NT 256   // 2 threads per tag

__device__ __forceinline__ void ffma2(unsigned long long& d,
                                      unsigned long long a,
                                      unsigned long long b) {
    asm("fma.rn.f32x2 %0, %1, %2, %0;" : "+l"(d) : "l"(a), "l"(b));
}
__device__ __forceinline__ void fadd2(unsigned long long& d, unsigned long long a) {
    asm("add.rn.f32x2 %0, %0, %1;" : "+l"(d) : "l"(a));
}
__device__ __forceinline__ unsigned long long pack2(float a, float b) {
    unsigned long long r;
    asm("mov.b64 %0, {%1, %2};" : "=l"(r) : "f"(a), "f"(b));
    return r;
}
__device__ __forceinline__ float2 unpack2(unsigned long long v) {
    float2 r;
    asm("mov.b64 {%0, %1}, %2;" : "=f"(r.x), "=f"(r.y) : "l"(v));
    return r;
}

// One CTA per batch; 2 threads per tag, halves combined with one warp shuffle.
// Lane l and lane l^16 of the same warp own tag n = (w<<4)|(l&15); half h = l>>4
// owns taps [64h, 64h+64). Scaled linear space with exact power-of-2 rescale.
__global__ __launch_bounds__(NT, 1)
void crf_fwd(const float* __restrict__ emissions,
             const int* __restrict__ token_sizes,
             const float* __restrict__ transitions,
             const float* __restrict__ head,
             const float* __restrict__ last,
             float* __restrict__ out)
{
    const int b    = blockIdx.x;
    const int tid  = threadIdx.x;
    const int w    = tid >> 5;
    const int lane = tid & 31;
    const int n    = (w << 4) | (lane & 15);
    const int h    = lane >> 4;

    __shared__ __align__(16) float W[2][Nv];
    __shared__ float red[4];

    // 32 packed f32x2 regs: exp(trans[j][n]) for taps j in [64h, 64h+64).
    unsigned long long e2[32];
    #pragma unroll
    for (int k = 0; k < 32; ++k) {
        int j = 64 * h + 2 * k;
        float lo = __expf(transitions[(j + 0) * Nv + n]);
        float hi = __expf(transitions[(j + 1) * Nv + n]);
        e2[k] = pack2(lo, hi);
    }

    const int len = token_sizes[b];
    const float* em = emissions + (size_t)b * Tv * Nv + n;

    // t = 0: alpha0 = head + em[0]; normalize by K = alpha0[0].
    float a0 = head[n] + em[0];
    if (h == 0) W[0][n] = a0;
    __syncthreads();
    float K = W[0][0];
    float logM = K;
    if (h == 0) W[1][n] = __expf(a0 - K);
    __syncthreads();
    int p = 1;

    // Distance-2 emission prefetch (both halves duplicate; loads coalesce/broadcast).
    float ex = __expf(em[Nv]);                  // exp(em) for t = 1
    float nx = em[min(2, Tv - 1) * Nv];         // raw em for t = 2

    for (int t = 1; t < len; ++t) {
        float w0 = W[p][0];                     // broadcast LDS for rescale

        // 64-tap half dot product: 16 LDS.128, 32 FFMA2, 4 accumulators.
        const ulonglong2* Wv = reinterpret_cast<const ulonglong2*>(W[p] + 64 * h);
        unsigned long long s0 = 0ull, s1 = 0ull, s2 = 0ull, s3 = 0ull;
        #pragma unroll
        for (int k = 0; k < 16; ++k) {
            ulonglong2 wv = Wv[k];
            if ((k & 1) == 0) { ffma2(s0, wv.x, e2[2 * k]); ffma2(s1, wv.y, e2[2 * k + 1]); }
            else              { ffma2(s2, wv.x, e2[2 * k]); ffma2(s3, wv.y, e2[2 * k + 1]); }
        }
        fadd2(s0, s1); fadd2(s2, s3); fadd2(s0, s2);
        float2 sp = unpack2(s0);
        float s = sp.x + sp.y;

        // Combine halves: lanes l and l^16 share tag n (warp-local, no barrier).
        s += __shfl_xor_sync(0xffffffffu, s, 16);

        // Exact power-of-2 rescale from previous W[0]'s exponent (no MUFU).
        int ebits = __float_as_int(w0) & 0x7f800000;
        float inv_r = __int_as_float(0x7f000000 - ebits);      // 2^(127 - E)
        logM += (float)((ebits >> 23) - 127) * 0.693147180559945f;

        float val = s * (ex * inv_r);
        if (h == 0) W[p ^ 1][n] = val;

        // Advance emission pipeline (clamped; value unused past len).
        ex = __expf(nx);
        nx = em[min(t + 2, Tv - 1) * Nv];

        __syncthreads();
        p ^= 1;
    }

    // Finalize: out = logM + log(sum_n W[n] * exp(last[n])). logM identical in
    // every thread (same w0 sequence), so warps 0-3 can reduce directly.
    if (tid < Nv) {
        float term = W[p][tid] * __expf(last[tid]);
        #pragma unroll
        for (int o = 16; o > 0; o >>= 1)
            term += __shfl_down_sync(0xffffffffu, term, o);
        if (lane == 0) red[w] = term;
    }
    __syncthreads();
    if (tid == 0) {
        float tot = (red[0] + red[1]) + (red[2] + red[3]);
        out[b] = logM + logf(tot);
    }
}

extern "C" void kernel_launch(void* const* d_in, const int* in_sizes, int n_in,
                              void* d_out, int out_size) {
    const float* emissions   = (const float*)d_in[0];
    const int*   token_sizes = (const int*)d_in[1];
    const float* transitions = (const float*)d_in[2];
    const float* head        = (const float*)d_in[3];
    const float* last        = (const float*)d_in[4];
    crf_fwd<<<Bv, NT>>>(emissions, token_sizes, transitions, head, last,
                        (float*)d_out);
}

// round 7
// speedup vs baseline: 1.7140x; 1.2218x over previous
#include <cuda_runtime.h>

#define Bv 64
#define Tv 2048
#define Cv 1
#define Nv 128

__device__ __forceinline__ void ffma2(unsigned long long& d,
                                      unsigned long long a,
                                      unsigned long long b) {
    asm("fma.rn.f32x2 %0, %1, %2, %0;" : "+l"(d) : "l"(a), "l"(b));
}
__device__ __forceinline__ void fadd2(unsigned long long& d, unsigned long long a) {
    asm("add.rn.f32x2 %0, %0, %1;" : "+l"(d) : "l"(a));
}
__device__ __forceinline__ unsigned long long pack2(float a, float b) {
    unsigned long long r;
    asm("mov.b64 %0, {%1, %2};" : "=l"(r) : "f"(a), "f"(b));
    return r;
}
__device__ __forceinline__ float2 unpack2(unsigned long long v) {
    float2 r;
    asm("mov.b64 {%0, %1}, %2;" : "=f"(r.x), "=f"(r.y) : "l"(v));
    return r;
}
__device__ __forceinline__ float lo32(unsigned long long v) {
    float r;
    asm("{ .reg .f32 hi; mov.b64 {%0, hi}, %1; }" : "=f"(r) : "l"(v));
    return r;
}

// One CTA per batch; thread n owns output tag n (R3 structure).
// Scaled linear space: alpha_t[n] = logM + log(W_t[n]); exact power-of-2 rescale.
// Emission loads use a DEPTH-4 prefetch pipeline: em[t+5] is loaded at step t and
// exp'd at step t+4 (~4 barrier windows ≈ 1100+ cyc), covering NAT-clock DRAM
// latency (~1000 cyc) that a distance-1 pipeline exposed every step.
__global__ __launch_bounds__(Nv, 1)
void crf_fwd(const float* __restrict__ emissions,
             const int* __restrict__ token_sizes,
             const float* __restrict__ transitions,
             const float* __restrict__ head,
             const float* __restrict__ last,
             float* __restrict__ out)
{
    const int b = blockIdx.x;
    const int n = threadIdx.x;

    __shared__ __align__(16) float W[2][Nv];
    __shared__ float red[4];

    // Pack column n of exp(transitions) as 64 f32x2 register pairs.
    unsigned long long e2[Nv / 2];
    #pragma unroll
    for (int k = 0; k < Nv / 2; ++k) {
        float lo = __expf(transitions[(2 * k + 0) * Nv + n]);
        float hi = __expf(transitions[(2 * k + 1) * Nv + n]);
        e2[k] = pack2(lo, hi);
    }

    const int len = token_sizes[b];
    const int ts = Cv * Nv;
    const float* em = emissions + (size_t)b * Tv * ts + n;

    // t = 0: alpha0 = head + em[0]; normalize by K = alpha0[0].
    float a0 = head[n] + em[0];
    W[0][n] = a0;
    __syncthreads();
    float K = W[0][0];
    float logM = K;
    W[1][n] = __expf(a0 - K);
    __syncthreads();
    int p = 1;

    // Depth-4 raw-emission prefetch pipeline. r0..r3 hold em[t+1..t+4] at the
    // top of step t. Clamped indices stay in-bounds; values unused past len.
    float ex = __expf(em[1 * ts]);                 // exp(em) for t = 1
    float r0 = em[min(2, Tv - 1) * ts];
    float r1 = em[min(3, Tv - 1) * ts];
    float r2 = em[min(4, Tv - 1) * ts];
    float r3 = em[min(5, Tv - 1) * ts];

    for (int t = 1; t < len; ++t) {
        // Hoisted: next step's exp and this step's far prefetch issue first,
        // hiding MUFU/LDG latency under the dot-product issue stream.
        float ex_next = __expf(r0);
        float r_new = em[min(t + 5, Tv - 1) * ts];

        const ulonglong2* Wv = reinterpret_cast<const ulonglong2*>(W[p]);

        // Peel k = 0: first LDS.128 also yields w0 = W[p][0] for the rescale.
        ulonglong2 w = Wv[0];
        float w0 = lo32(w.x);
        unsigned long long s0 = 0ull, s1 = 0ull, s2 = 0ull, s3 = 0ull;
        ffma2(s0, w.x, e2[0]);
        ffma2(s1, w.y, e2[1]);

        #pragma unroll
        for (int k = 1; k < Nv / 4; ++k) {          // 31 more LDS.128, 62 FFMA2
            w = Wv[k];
            if ((k & 1) == 0) { ffma2(s0, w.x, e2[2 * k]); ffma2(s1, w.y, e2[2 * k + 1]); }
            else              { ffma2(s2, w.x, e2[2 * k]); ffma2(s3, w.y, e2[2 * k + 1]); }
        }
        fadd2(s0, s1); fadd2(s2, s3); fadd2(s0, s2);
        float2 sp = unpack2(s0);
        float s = sp.x + sp.y;

        // Exact power-of-2 rescale from previous W[0]'s exponent (no MUFU).
        int ebits = __float_as_int(w0) & 0x7f800000;
        float inv_r = __int_as_float(0x7f000000 - ebits);      // 2^(127 - E)
        logM += (float)((ebits >> 23) - 127) * 0.693147180559945f;

        W[p ^ 1][n] = s * (ex * inv_r);

        // Rotate prefetch pipeline.
        ex = ex_next;
        r0 = r1; r1 = r2; r2 = r3; r3 = r_new;

        __syncthreads();
        p ^= 1;
    }

    // Finalize: out = logM + log(sum_n W[n] * exp(last[n]))
    float term = W[p][n] * __expf(last[n]);
    #pragma unroll
    for (int o = 16; o > 0; o >>= 1)
        term += __shfl_down_sync(0xffffffffu, term, o);
    if ((n & 31) == 0) red[n >> 5] = term;
    __syncthreads();
    if (n == 0) {
        float tot = (red[0] + red[1]) + (red[2] + red[3]);
        out[b] = logM + logf(tot);
    }
}

extern "C" void kernel_launch(void* const* d_in, const int* in_sizes, int n_in,
                              void* d_out, int out_size) {
    const float* emissions   = (const float*)d_in[0];
    const int*   token_sizes = (const int*)d_in[1];
    const float* transitions = (const float*)d_in[2];
    const float* head        = (const float*)d_in[3];
    const float* last        = (const float*)d_in[4];
    crf_fwd<<<Bv, Nv>>>(emissions, token_sizes, transitions, head, last,
                        (float*)d_out);
}